// round 13
// baseline (speedup 1.0000x reference)
#include <cuda_runtime.h>
#include <stdint.h>

#define NUM_FIELDS 10
#define VOCAB      100000
#define EMBED      16            // floats per embedding row (64 bytes)
#define BATCH      16384
#define NPAIRS     45            // C(10,2)
#define NPGRP      23            // ceil(45/2) pair-groups
#define B_PER_BLK  32            // b values per block (each covered by 2 pairs)

// triu_indices(10, k=1): pair p -> (ii[p], jj[p]) with ii < jj
__constant__ unsigned char c_ii[NPAIRS] = {
    0,0,0,0,0,0,0,0,0,
    1,1,1,1,1,1,1,1,
    2,2,2,2,2,2,2,
    3,3,3,3,3,3,
    4,4,4,4,4,
    5,5,5,5,
    6,6,6,
    7,7,
    8
};
__constant__ unsigned char c_jj[NPAIRS] = {
    1,2,3,4,5,6,7,8,9,
    2,3,4,5,6,7,8,9,
    3,4,5,6,7,8,9,
    4,5,6,7,8,9,
    5,6,7,8,9,
    6,7,8,9,
    7,8,9,
    8,9,
    9
};

// PAIR-GROUP blocks: blockIdx.y = pair group (p0=2y, p1=2y+1).
// Within one 256-thread block, quads 0..31 process p0 and quads 32..63
// process p1 for the SAME 32 b values. Both 64B halves of each 128B
// output line (chunks p0,p1 of row b) are therefore written by the same
// block within a short window -> full-line dirty merge in L2, single
// writeback, no partial-line fill. (Previously the two halves were
// written by different CTAs far apart in time -> ~2x line traffic.)
// Read side keeps R6's pair-major locality (~4-5 live pair slots).
__global__ __launch_bounds__(256)
void ffm_kernel(const int*    __restrict__ x,      // int32 (16384, 10)
                const float4* __restrict__ emb,    // (10, 1e6, 16) as float4[40M]
                float4*       __restrict__ out)    // (16384, 45, 16) as float4
{
    int q    = threadIdx.x & 3;                    // float4 within 64B chunk
    int quad = threadIdx.x >> 2;                   // 0..63
    int b    = blockIdx.x * B_PER_BLK + (quad & 31);   // 512*32 = 16384 exact
    int ph   = quad >> 5;                          // 0 -> p0, 1 -> p1
    int p    = blockIdx.y * 2 + ph;

    if (p >= NPAIRS) return;                       // last group has only p=44

    int i = c_ii[p];
    int j = c_jj[p];

    // broadcast within quad
    int xi = x[b * NUM_FIELDS + i];
    int xj = x[b * NUM_FIELDS + j];
    xi = min(max(xi, 0), VOCAB - 1);
    xj = min(max(xj, 0), VOCAB - 1);

    // out[b,p] = emb[j, x[b,i]+i*V] * emb[i, x[b,j]+j*V]
    size_t rowA = (size_t)j * (NUM_FIELDS * (size_t)VOCAB) + (size_t)xi + (size_t)i * VOCAB;
    size_t rowB = (size_t)i * (NUM_FIELDS * (size_t)VOCAB) + (size_t)xj + (size_t)j * VOCAB;

    // Streaming loads: rows are used exactly once within a launch.
    float4 a = __ldcs(emb + rowA * (EMBED / 4) + q);
    float4 v = __ldcs(emb + rowB * (EMBED / 4) + q);

    float4 o;
    o.x = a.x * v.x;
    o.y = a.y * v.y;
    o.z = a.z * v.z;
    o.w = a.w * v.w;

    // Evict-first allocating store: lets the two 64B halves of the line
    // merge in L2 and write back as one full line.
    __stcs(out + ((size_t)b * NPAIRS + p) * (EMBED / 4) + q, o);
}

extern "C" void kernel_launch(void* const* d_in, const int* in_sizes, int n_in,
                              void* d_out, int out_size)
{
    const int*    x   = (const int*)d_in[0];      // indices (int32 on device)
    const float4* emb = (const float4*)d_in[1];   // float32 (10, 1e6, 16)
    float4*       out = (float4*)d_out;           // float32 (16384, 45, 16)

    dim3 grid(BATCH / B_PER_BLK, NPGRP);          // (512, 23)
    ffm_kernel<<<grid, 256>>>(x, emb, out);
}

// round 14
// speedup vs baseline: 1.0138x; 1.0138x over previous
#include <cuda_runtime.h>
#include <stdint.h>

#define NUM_FIELDS 10
#define VOCAB      100000
#define EMBED      16            // floats per embedding row (64 bytes)
#define BATCH      16384
#define NPAIRS     45            // C(10,2)
#define BLOCK      128
#define B_PER_BLK  (BLOCK / 4)   // 32 quads per block

// triu_indices(10, k=1): pair p -> (ii[p], jj[p]) with ii < jj
__constant__ unsigned char c_ii[NPAIRS] = {
    0,0,0,0,0,0,0,0,0,
    1,1,1,1,1,1,1,1,
    2,2,2,2,2,2,2,
    3,3,3,3,3,3,
    4,4,4,4,4,
    5,5,5,5,
    6,6,6,
    7,7,
    8
};
__constant__ unsigned char c_jj[NPAIRS] = {
    1,2,3,4,5,6,7,8,9,
    2,3,4,5,6,7,8,9,
    3,4,5,6,7,8,9,
    4,5,6,7,8,9,
    5,6,7,8,9,
    6,7,8,9,
    7,8,9,
    8,9,
    9
};

// FINAL (R10) configuration — measured best on both ncu dur (31.9us) and
// stable bench (34.7us):
//   * PAIR-MAJOR grid, 128-thread blocks: resident CTAs span ~2.3 pair
//     slots (~30MB live gather footprint) -> best DRAM-row/TLB locality
//     (64- and 256-thread variants both measured worse).
//   * __ldcs gathers: rows used exactly once, evict-first streaming.
//   * __stwt stores: write-through, no L2 allocate -> lowest HBM bytes
//     (~170MB vs ~182MB with allocating stores).
//   * 4 lanes per (b,p): lane q handles float4 q of both rows -> each 64B
//     row fetched by one LDG wavefront; stores coalesced.
// Kernel is pinned at the random-64B-gather DRAM roofline (~170MB @
// ~5.3TB/s); every byte- and layout-lever beyond this measured neutral
// or worse (R4/R5/R7/R11/R12/R13 experiments).
__global__ __launch_bounds__(BLOCK)
void ffm_kernel(const int*    __restrict__ x,      // int32 (16384, 10)
                const float4* __restrict__ emb,    // (10, 1e6, 16) as float4[40M]
                float4*       __restrict__ out)    // (16384, 45, 16) as float4
{
    int q    = threadIdx.x & 3;
    int quad = threadIdx.x >> 2;                   // 0..31
    int b    = blockIdx.x * B_PER_BLK + quad;      // exact fit: 512*32 = 16384
    int p    = blockIdx.y;                         // uniform per block
    int i    = c_ii[p];
    int j    = c_jj[p];

    // broadcast within quad
    int xi = x[b * NUM_FIELDS + i];
    int xj = x[b * NUM_FIELDS + j];
    xi = min(max(xi, 0), VOCAB - 1);
    xj = min(max(xj, 0), VOCAB - 1);

    // out[b,p] = emb[j, x[b,i]+i*V] * emb[i, x[b,j]+j*V]
    size_t rowA = (size_t)j * (NUM_FIELDS * (size_t)VOCAB) + (size_t)xi + (size_t)i * VOCAB;
    size_t rowB = (size_t)i * (NUM_FIELDS * (size_t)VOCAB) + (size_t)xj + (size_t)j * VOCAB;

    // Streaming loads: rows are used exactly once.
    float4 a = __ldcs(emb + rowA * (EMBED / 4) + q);
    float4 v = __ldcs(emb + rowB * (EMBED / 4) + q);

    float4 o;
    o.x = a.x * v.x;
    o.y = a.y * v.y;
    o.z = a.z * v.z;
    o.w = a.w * v.w;

    // Write-through, no L2 allocate: output is never read back.
    __stwt(out + ((size_t)b * NPAIRS + p) * (EMBED / 4) + q, o);
}

extern "C" void kernel_launch(void* const* d_in, const int* in_sizes, int n_in,
                              void* d_out, int out_size)
{
    const int*    x   = (const int*)d_in[0];      // indices (int32 on device)
    const float4* emb = (const float4*)d_in[1];   // float32 (10, 1e6, 16)
    float4*       out = (float4*)d_out;           // float32 (16384, 45, 16)

    dim3 grid(BATCH / B_PER_BLK, NPAIRS);         // (512, 45)
    ffm_kernel<<<grid, BLOCK>>>(x, emb, out);
}